// round 2
// baseline (speedup 1.0000x reference)
#include <cuda_runtime.h>
#include <cuda_fp16.h>
#include <cstdint>

#define BATCH 8192
#define INF   4096
#define OUTF  4096
#define BS    64
#define NBR   64
#define BPR   16
#define TM    128
#define NT_M  (BATCH / TM)          // 64
#define STAGES 3
#define XT_BYTES (TM * BS * 2)      // 16384
#define WT_BYTES (BS * BS * 2)      // 8192
#define SMEM_SZ (STAGES * (XT_BYTES + WT_BYTES))   // 73728
#define W_BASE (STAGES * XT_BYTES)  // 49152

// Scratch (device globals; allocation-free)
__device__ __half g_xh[(size_t)BATCH * INF];            // fp16 x, row-major
__device__ __half g_wt[(size_t)NBR * BPR * BS * BS];    // fp16 W, [blk][b][o]

// ---------------- prepass: x fp32 -> fp16 ----------------
__global__ void conv_x_kernel(const float* __restrict__ x) {
    size_t i = ((size_t)blockIdx.x * 256 + threadIdx.x) * 8;
    float4 a = *(const float4*)(x + i);
    float4 b = *(const float4*)(x + i + 4);
    __half2 h0 = __floats2half2_rn(a.x, a.y);
    __half2 h1 = __floats2half2_rn(a.z, a.w);
    __half2 h2 = __floats2half2_rn(b.x, b.y);
    __half2 h3 = __floats2half2_rn(b.z, b.w);
    uint4 o;
    o.x = *(uint32_t*)&h0; o.y = *(uint32_t*)&h1;
    o.z = *(uint32_t*)&h2; o.w = *(uint32_t*)&h3;
    *(uint4*)(g_xh + i) = o;
}

// ---------------- prepass: W fp32 [blk][o][b] -> fp16 [blk][b][o] ----------------
__global__ void conv_w_kernel(const float* __restrict__ v) {
    __shared__ float t[64][65];
    int blk = blockIdx.x;
    int tid = threadIdx.x;
    const float* src = v + (size_t)blk * 4096;
    #pragma unroll
    for (int k = 0; k < 16; k++) {
        int r = k * 4 + (tid >> 6);
        int c = tid & 63;
        t[r][c] = src[r * 64 + c];
    }
    __syncthreads();
    __half* dst = g_wt + (size_t)blk * 4096;
    #pragma unroll
    for (int k = 0; k < 16; k++) {
        int b = k * 4 + (tid >> 6);
        int o = tid & 63;
        dst[b * 64 + o] = __float2half(t[o][b]);
    }
}

// ---------------- PTX helpers ----------------
__device__ __forceinline__ uint32_t smem_u32(const void* p) {
    uint32_t a;
    asm("{ .reg .u64 t; cvta.to.shared.u64 t, %1; cvt.u32.u64 %0, t; }" : "=r"(a) : "l"(p));
    return a;
}
__device__ __forceinline__ void cp16(uint32_t s, const void* g) {
    asm volatile("cp.async.cg.shared.global [%0], [%1], 16;" :: "r"(s), "l"(g));
}
__device__ __forceinline__ void cp_commit() {
    asm volatile("cp.async.commit_group;");
}
__device__ __forceinline__ void ldsm4(uint32_t* d, uint32_t a) {
    asm volatile("ldmatrix.sync.aligned.m8n8.x4.shared.b16 {%0,%1,%2,%3}, [%4];"
                 : "=r"(d[0]), "=r"(d[1]), "=r"(d[2]), "=r"(d[3]) : "r"(a));
}
__device__ __forceinline__ void ldsm4t(uint32_t* d, uint32_t a) {
    asm volatile("ldmatrix.sync.aligned.m8n8.x4.trans.shared.b16 {%0,%1,%2,%3}, [%4];"
                 : "=r"(d[0]), "=r"(d[1]), "=r"(d[2]), "=r"(d[3]) : "r"(a));
}
__device__ __forceinline__ void mma16816(float* c, const uint32_t* a, const uint32_t* b) {
    asm volatile(
        "mma.sync.aligned.m16n8k16.row.col.f32.f16.f16.f32 "
        "{%0,%1,%2,%3}, {%4,%5,%6,%7}, {%8,%9}, {%0,%1,%2,%3};"
        : "+f"(c[0]), "+f"(c[1]), "+f"(c[2]), "+f"(c[3])
        : "r"(a[0]), "r"(a[1]), "r"(a[2]), "r"(a[3]), "r"(b[0]), "r"(b[1]));
}

// ---------------- main kernel ----------------
__global__ void __launch_bounds__(256, 2)
bsr_main_kernel(const float* __restrict__ bias, const int* __restrict__ cols,
                float* __restrict__ out) {
    extern __shared__ char smem[];
    const uint32_t sb = smem_u32(smem);
    const int r  = blockIdx.x;   // row-block 0..63
    const int mt = blockIdx.y;   // batch tile 0..63
    const int tid = threadIdx.x;
    const int warp = tid >> 5;
    const int lane = tid & 31;
    const int wm = warp >> 1;    // 0..3 (m)
    const int wn = warp & 1;     // 0..1 (n)

    int cidx[BPR];
    #pragma unroll
    for (int j = 0; j < BPR; j++) cidx[j] = __ldg(&cols[r * BPR + j]);

    const __half* xg = g_xh + (size_t)mt * TM * INF;
    const __half* wg = g_wt + (size_t)r * BPR * BS * BS;

    float acc[2][4][4];
    #pragma unroll
    for (int mi = 0; mi < 2; mi++)
        #pragma unroll
        for (int ni = 0; ni < 4; ni++)
            #pragma unroll
            for (int q = 0; q < 4; q++) acc[mi][ni][q] = 0.0f;

    // load issuer
    auto issue = [&](int j) {
        int s = j % STAGES;
        int c = cidx[j];
        const char* xsrc = (const char*)(xg + (size_t)c * BS);
        uint32_t xs = sb + s * XT_BYTES;
        #pragma unroll
        for (int k = 0; k < 4; k++) {
            int q = tid + k * 256;          // 0..1023
            int row = q >> 3, ch = q & 7;
            cp16(xs + row * 128 + ((ch ^ (row & 7)) << 4),
                 xsrc + (size_t)row * (INF * 2) + ch * 16);
        }
        const char* wsrc = (const char*)(wg + (size_t)j * BS * BS);
        uint32_t ws = sb + W_BASE + s * WT_BYTES;
        #pragma unroll
        for (int k = 0; k < 2; k++) {
            int q = tid + k * 256;          // 0..511
            int row = q >> 3, ch = q & 7;
            cp16(ws + row * 128 + ((ch ^ (row & 7)) << 4),
                 wsrc + row * 128 + ch * 16);
        }
        cp_commit();
    };

    issue(0);
    issue(1);

    const int mat = lane >> 3;   // 0..3
    const int rl  = lane & 7;

    for (int j = 0; j < BPR; j++) {
        if (j < BPR - 2) asm volatile("cp.async.wait_group 1;");
        else             asm volatile("cp.async.wait_group 0;");
        __syncthreads();

        uint32_t xs = sb + (j % STAGES) * XT_BYTES;
        uint32_t ws = sb + W_BASE + (j % STAGES) * WT_BYTES;

        #pragma unroll
        for (int ks = 0; ks < 4; ks++) {
            uint32_t a[2][4];
            uint32_t b[4][2];
            #pragma unroll
            for (int mi = 0; mi < 2; mi++) {
                int row = wm * 32 + mi * 16 + (mat & 1) * 8 + rl;
                int ch = 2 * ks + (mat >> 1);
                ldsm4(a[mi], xs + row * 128 + ((ch ^ (row & 7)) << 4));
            }
            #pragma unroll
            for (int nh = 0; nh < 2; nh++) {
                int krow = ks * 16 + (mat & 1) * 8 + rl;
                int nch = (wn * 32 >> 3) + nh * 2 + (mat >> 1);
                uint32_t t[4];
                ldsm4t(t, ws + krow * 128 + ((nch ^ (krow & 7)) << 4));
                b[nh * 2][0] = t[0];     b[nh * 2][1] = t[1];
                b[nh * 2 + 1][0] = t[2]; b[nh * 2 + 1][1] = t[3];
            }
            #pragma unroll
            for (int mi = 0; mi < 2; mi++)
                #pragma unroll
                for (int ni = 0; ni < 4; ni++)
                    mma16816(acc[mi][ni], a[mi], b[ni]);
        }

        if (j + 2 < BPR) issue(j + 2);
    }

    // epilogue: add bias, write fp32
    #pragma unroll
    for (int mi = 0; mi < 2; mi++) {
        #pragma unroll
        for (int ni = 0; ni < 4; ni++) {
            int rr = mt * TM + wm * 32 + mi * 16 + (lane >> 2);
            int cc = r * BS + wn * 32 + ni * 8 + 2 * (lane & 3);
            float2 bv = *(const float2*)(bias + cc);
            float2 v0, v1;
            v0.x = acc[mi][ni][0] + bv.x;
            v0.y = acc[mi][ni][1] + bv.y;
            v1.x = acc[mi][ni][2] + bv.x;
            v1.y = acc[mi][ni][3] + bv.y;
            *(float2*)(out + (size_t)rr * OUTF + cc) = v0;
            *(float2*)(out + (size_t)(rr + 8) * OUTF + cc) = v1;
        }
    }
}

// ---------------- launch ----------------
extern "C" void kernel_launch(void* const* d_in, const int* in_sizes, int n_in,
                              void* d_out, int out_size) {
    const float* x      = (const float*)d_in[0];
    const float* values = (const float*)d_in[1];
    const float* bias   = (const float*)d_in[2];
    const int*   cols   = (const int*)d_in[3];
    float* out = (float*)d_out;

    conv_x_kernel<<<(BATCH * (size_t)INF / 8) / 256, 256>>>(x);
    conv_w_kernel<<<NBR * BPR, 256>>>(values);

    static int configured = 0;
    cudaFuncSetAttribute(bsr_main_kernel,
                         cudaFuncAttributeMaxDynamicSharedMemorySize, SMEM_SZ);
    (void)configured;
    bsr_main_kernel<<<dim3(NBR, NT_M), 256, SMEM_SZ>>>(bias, cols, out);
}